// round 16
// baseline (speedup 1.0000x reference)
#include <cuda_runtime.h>
#include <cuda_fp16.h>
#include <math.h>
#include <stdint.h>

#define B_  8
#define Q_  512
#define D_  4096
#define H_  1024

// ---- big-tile kernel (GEMM1, GEMM3): CTA 128x128, warp 32x64, BK=64, 2 CTA/SM
#define STAGES  3
#define TILE    128
#define BK      64
#define STRD_H  72
#define STRD_BN 136
#define A_HALVES (TILE * STRD_H)           // 9216
#define B_REGION 9216
#define STAGE_HALVES (A_HALVES + B_REGION) // 18432
#define SMEM_BYTES (STAGES * STAGE_HALVES * 2)   // 110592

// ---- small-tile kernel (GEMM2): CTA 128x64, warp 32x32, BK=32, 3 CTA/SM
#define S_BK      32
#define S_STRD    40
#define S_A_HALVES (128 * S_STRD)              // 5120
#define S_B_REGION (64 * S_STRD)               // 2560
#define S_STAGE (S_A_HALVES + S_B_REGION)      // 7680
#define S_SMEM_BYTES (STAGES * S_STAGE * 2)    // 46080

// ---------------- scratch (static device memory; no allocs allowed) ----------
__device__ __align__(16) __half g_q16[(size_t)B_ * Q_ * H_];
__device__ __align__(16) __half g_query16[(size_t)B_ * Q_ * H_];
__device__ __align__(16) __half g_W16[(size_t)H_ * H_];
__device__ __align__(16) __half g_doc16[(size_t)B_ * D_ * H_];
__device__ __align__(16) __half g_attn16[(size_t)B_ * Q_ * D_];
__device__ float g_mx[B_ * Q_];
__device__ float g_inv[B_ * Q_];

// ---------------- helpers -----------------------------------------------------
__device__ __forceinline__ void cp_async16(uint32_t dst, const void* src) {
    asm volatile("cp.async.cg.shared.global [%0], [%1], 16;" :: "r"(dst), "l"(src));
}
#define CP_COMMIT() asm volatile("cp.async.commit_group;" ::: "memory")
#define CP_WAIT(n)  asm volatile("cp.async.wait_group %0;" :: "n"(n) : "memory")

__device__ __forceinline__ uint32_t smem_u32(const void* p) {
    uint32_t a;
    asm("{ .reg .u64 t; cvta.to.shared.u64 t, %1; cvt.u32.u64 %0, t; }" : "=r"(a) : "l"(p));
    return a;
}

__device__ __forceinline__ void ldsm_x4(uint32_t* r, uint32_t addr) {
    asm volatile("ldmatrix.sync.aligned.m8n8.x4.shared.b16 {%0,%1,%2,%3}, [%4];"
                 : "=r"(r[0]), "=r"(r[1]), "=r"(r[2]), "=r"(r[3]) : "r"(addr));
}
__device__ __forceinline__ void ldsm_x4_t(uint32_t* r, uint32_t addr) {
    asm volatile("ldmatrix.sync.aligned.m8n8.x4.trans.shared.b16 {%0,%1,%2,%3}, [%4];"
                 : "=r"(r[0]), "=r"(r[1]), "=r"(r[2]), "=r"(r[3]) : "r"(addr));
}

__device__ __forceinline__ void mma_f16(float* c, const uint32_t* a, const uint32_t* b) {
    asm volatile(
        "mma.sync.aligned.m16n8k16.row.col.f32.f16.f16.f32 "
        "{%0,%1,%2,%3}, {%4,%5,%6,%7}, {%8,%9}, {%0,%1,%2,%3};"
        : "+f"(c[0]), "+f"(c[1]), "+f"(c[2]), "+f"(c[3])
        : "r"(a[0]), "r"(a[1]), "r"(a[2]), "r"(a[3]), "r"(b[0]), "r"(b[1]));
}

// ---------------- big-tile warp-MMA FP16 GEMM (GEMM1, GEMM3) ------------------
template <bool B_TRANS, bool HAS_BIAS, bool OUT_HALF>
__global__ void __launch_bounds__(256, 2) wgemm_h(
    const __half* __restrict__ A, const __half* __restrict__ Bm,
    void* __restrict__ Cv, const float* __restrict__ bias,
    int K, int lda, int ldb, int ldc, float alpha,
    size_t strideA, size_t strideB, size_t strideC)
{
    extern __shared__ __half smh[];
    const uint32_t sbase = smem_u32(smh);

    const int tid  = threadIdx.x;
    const int lane = tid & 31;
    const int wid  = tid >> 5;
    const int gid  = lane >> 2;
    const int tig  = lane & 3;
    const int warp_m = (wid & 3) * 32;
    const int warp_n = (wid >> 2) * 64;

    const size_t batch = blockIdx.z;
    const __half* Ab = A + batch * strideA + (size_t)(blockIdx.y * TILE) * lda;
    const __half* Bb;
    if (B_TRANS)
        Bb = Bm + batch * strideB + blockIdx.x * TILE;
    else
        Bb = Bm + batch * strideB + (size_t)(blockIdx.x * TILE) * ldb;

    const uint32_t offA = ((uint32_t)(warp_m + (lane & 15)) * STRD_H + ((lane >> 4) << 3)) * 2;
    const uint32_t offB = ((uint32_t)(warp_n + ((lane >> 4) << 3) + (lane & 7)) * STRD_H + (lane & 8)) * 2
                          + A_HALVES * 2;
    const uint32_t offBT = ((uint32_t)((lane & 7) + ((lane >> 3) & 1) * 8) * STRD_BN
                            + warp_n + ((lane >> 4) << 3)) * 2
                          + A_HALVES * 2;

    float acc[2][8][4];
#pragma unroll
    for (int mt = 0; mt < 2; mt++)
#pragma unroll
        for (int nt = 0; nt < 8; nt++)
#pragma unroll
            for (int i = 0; i < 4; i++) acc[mt][nt][i] = 0.0f;

    const int NK = K / BK;

    auto load_stage = [&](int kb) {
        const int s = kb % STAGES;
        const uint32_t stA = sbase + s * STAGE_HALVES * 2;
        const uint32_t stB = stA + A_HALVES * 2;
        const __half* gA = Ab + kb * BK;
#pragma unroll
        for (int r = 0; r < 4; r++) {
            const int c = tid + r * 256;
            const int rw = c >> 3, q = (c & 7) * 8;
            cp_async16(stA + (rw * STRD_H + q) * 2, gA + (size_t)rw * lda + q);
        }
        if (B_TRANS) {
            const __half* gB = Bb + (size_t)(kb * BK) * ldb;
#pragma unroll
            for (int r = 0; r < 4; r++) {
                const int c = tid + r * 256;
                const int rw = c >> 4, q = (c & 15) * 8;
                cp_async16(stB + (rw * STRD_BN + q) * 2, gB + (size_t)rw * ldb + q);
            }
        } else {
            const __half* gB = Bb + kb * BK;
#pragma unroll
            for (int r = 0; r < 4; r++) {
                const int c = tid + r * 256;
                const int rw = c >> 3, q = (c & 7) * 8;
                cp_async16(stB + (rw * STRD_H + q) * 2, gB + (size_t)rw * ldb + q);
            }
        }
    };

#pragma unroll
    for (int s = 0; s < STAGES - 1; s++) {
        load_stage(s);
        CP_COMMIT();
    }

    for (int kb = 0; kb < NK; kb++) {
        CP_WAIT(STAGES - 2);
        __syncthreads();

        const int kn = kb + STAGES - 1;
        if (kn < NK) load_stage(kn);
        CP_COMMIT();

        const uint32_t stOff = sbase + (kb % STAGES) * STAGE_HALVES * 2;
#pragma unroll
        for (int kk = 0; kk < BK; kk += 16) {
            uint32_t a[2][4], b[4][4];
#pragma unroll
            for (int mt = 0; mt < 2; mt++)
                ldsm_x4(a[mt], stOff + offA + (mt * 16 * STRD_H + kk) * 2);
#pragma unroll
            for (int p = 0; p < 4; p++) {
                if (B_TRANS)
                    ldsm_x4_t(b[p], stOff + offBT + (kk * STRD_BN + p * 16) * 2);
                else
                    ldsm_x4(b[p], stOff + offB + (p * 16 * STRD_H + kk) * 2);
            }
#pragma unroll
            for (int mt = 0; mt < 2; mt++)
#pragma unroll
                for (int p = 0; p < 4; p++) {
                    mma_f16(acc[mt][2 * p],     a[mt], &b[p][0]);
                    mma_f16(acc[mt][2 * p + 1], a[mt], &b[p][2]);
                }
        }
    }

#pragma unroll
    for (int mt = 0; mt < 2; mt++) {
        const int r0 = blockIdx.y * TILE + warp_m + mt * 16 + gid;
#pragma unroll
        for (int nt = 0; nt < 8; nt++) {
            const int col = blockIdx.x * TILE + warp_n + nt * 8 + 2 * tig;
            float bx = 0.f, by = 0.f;
            if (HAS_BIAS) { bx = __ldg(bias + col); by = __ldg(bias + col + 1); }
            float2 v0, v1;
            v0.x = acc[mt][nt][0] * alpha + bx;
            v0.y = acc[mt][nt][1] * alpha + by;
            v1.x = acc[mt][nt][2] * alpha + bx;
            v1.y = acc[mt][nt][3] * alpha + by;
            if (OUT_HALF) {
                __half* Cb = (__half*)Cv + batch * strideC;
                *(__half2*)(Cb + (size_t)r0 * ldc + col) = __floats2half2_rn(v0.x, v0.y);
                *(__half2*)(Cb + (size_t)(r0 + 8) * ldc + col) = __floats2half2_rn(v1.x, v1.y);
            } else {
                float* Cb = (float*)Cv + batch * strideC;
                *(float2*)(Cb + (size_t)r0 * ldc + col) = v0;
                *(float2*)(Cb + (size_t)(r0 + 8) * ldc + col) = v1;
            }
        }
    }
}

// ---------------- small-tile GEMM (GEMM2): CTA 128x64, warp 32x32, 3 CTA/SM ---
// C[m][n] = alpha * sum_k A[m][k] * B[n][k]; A,B K-major fp16.
__global__ void __launch_bounds__(256, 3) wgemm_s(
    const __half* __restrict__ A, const __half* __restrict__ Bm,
    float* __restrict__ C,
    int K, int lda, int ldb, int ldc, float alpha,
    size_t strideA, size_t strideB, size_t strideC)
{
    extern __shared__ __half smh[];
    const uint32_t sbase = smem_u32(smh);

    const int tid  = threadIdx.x;
    const int lane = tid & 31;
    const int wid  = tid >> 5;
    const int gid  = lane >> 2;
    const int tig  = lane & 3;
    const int warp_m = (wid & 3) * 32;   // 4 warps in M
    const int warp_n = (wid >> 2) * 32;  // 2 warps in N

    const size_t batch = blockIdx.z;
    const __half* Ab = A + batch * strideA + (size_t)(blockIdx.y * 128) * lda;
    const __half* Bb = Bm + batch * strideB + (size_t)(blockIdx.x * 64) * ldb;

    const uint32_t offA = ((uint32_t)(warp_m + (lane & 15)) * S_STRD + ((lane >> 4) << 3)) * 2;
    const uint32_t offB = ((uint32_t)(warp_n + ((lane >> 4) << 3) + (lane & 7)) * S_STRD + (lane & 8)) * 2
                          + S_A_HALVES * 2;

    float acc[2][4][4];
#pragma unroll
    for (int mt = 0; mt < 2; mt++)
#pragma unroll
        for (int nt = 0; nt < 4; nt++)
#pragma unroll
            for (int i = 0; i < 4; i++) acc[mt][nt][i] = 0.0f;

    const int NK = K / S_BK;

    auto load_stage = [&](int kb) {
        const int s = kb % STAGES;
        const uint32_t stA = sbase + s * S_STAGE * 2;
        const uint32_t stB = stA + S_A_HALVES * 2;
        const __half* gA = Ab + kb * S_BK;
        const __half* gB = Bb + kb * S_BK;
#pragma unroll
        for (int r = 0; r < 2; r++) {            // A: 128 rows x 4 chunks = 512
            const int c = tid + r * 256;
            const int rw = c >> 2, q = (c & 3) * 8;
            cp_async16(stA + (rw * S_STRD + q) * 2, gA + (size_t)rw * lda + q);
        }
        {                                        // B: 64 rows x 4 chunks = 256
            const int rw = tid >> 2, q = (tid & 3) * 8;
            cp_async16(stB + (rw * S_STRD + q) * 2, gB + (size_t)rw * ldb + q);
        }
    };

#pragma unroll
    for (int s = 0; s < STAGES - 1; s++) {
        load_stage(s);
        CP_COMMIT();
    }

    for (int kb = 0; kb < NK; kb++) {
        CP_WAIT(STAGES - 2);
        __syncthreads();

        const int kn = kb + STAGES - 1;
        if (kn < NK) load_stage(kn);
        CP_COMMIT();

        const uint32_t stOff = sbase + (kb % STAGES) * S_STAGE * 2;
#pragma unroll
        for (int kk = 0; kk < S_BK; kk += 16) {
            uint32_t a[2][4], b[2][4];
#pragma unroll
            for (int mt = 0; mt < 2; mt++)
                ldsm_x4(a[mt], stOff + offA + (mt * 16 * S_STRD + kk) * 2);
#pragma unroll
            for (int p = 0; p < 2; p++)
                ldsm_x4(b[p], stOff + offB + (p * 16 * S_STRD + kk) * 2);
#pragma unroll
            for (int mt = 0; mt < 2; mt++)
#pragma unroll
                for (int p = 0; p < 2; p++) {
                    mma_f16(acc[mt][2 * p],     a[mt], &b[p][0]);
                    mma_f16(acc[mt][2 * p + 1], a[mt], &b[p][2]);
                }
        }
    }

#pragma unroll
    for (int mt = 0; mt < 2; mt++) {
        const int r0 = blockIdx.y * 128 + warp_m + mt * 16 + gid;
#pragma unroll
        for (int nt = 0; nt < 4; nt++) {
            const int col = blockIdx.x * 64 + warp_n + nt * 8 + 2 * tig;
            float2 v0, v1;
            v0.x = acc[mt][nt][0] * alpha;
            v0.y = acc[mt][nt][1] * alpha;
            v1.x = acc[mt][nt][2] * alpha;
            v1.y = acc[mt][nt][3] * alpha;
            float* Cb = C + batch * strideC;
            *(float2*)(Cb + (size_t)r0 * ldc + col) = v0;
            *(float2*)(Cb + (size_t)(r0 + 8) * ldc + col) = v1;
        }
    }
}

// ---------------- prep: flat fp32 -> fp16 --------------------------------------
__global__ void k_cvt_h(const float* __restrict__ src, __half* __restrict__ dst) {
    size_t i = (size_t)blockIdx.x * blockDim.x + threadIdx.x;
    float4 v = ((const float4*)src)[i];
    ((__half2*)dst)[i * 2]     = __floats2half2_rn(v.x, v.y);
    ((__half2*)dst)[i * 2 + 1] = __floats2half2_rn(v.z, v.w);
}

// ---------------- softmax pass 1: stats + fp16 weights (critical path) ---------
__global__ void __launch_bounds__(256) softmax_p1(
    const float* __restrict__ attn, const int* __restrict__ mask,
    __half* __restrict__ attn16)
{
    const int row = blockIdx.x;
    const int b = row / Q_;
    const int4* mrow = (const int4*)(mask + (size_t)b * D_);
    const float4* s4 = (const float4*)(attn + (size_t)row * D_);
    __half2* h2 = (__half2*)(attn16 + (size_t)row * D_);
    const int tid = threadIdx.x;

    float v[16];
    float mx = -INFINITY;
#pragma unroll
    for (int i = 0; i < 4; i++) {
        const int c = tid + i * 256;
        int4 m = mrow[c];
        float4 x = s4[c];
        v[i * 4 + 0] = (m.x != 0) ? x.x : -INFINITY;
        v[i * 4 + 1] = (m.y != 0) ? x.y : -INFINITY;
        v[i * 4 + 2] = (m.z != 0) ? x.z : -INFINITY;
        v[i * 4 + 3] = (m.w != 0) ? x.w : -INFINITY;
        mx = fmaxf(mx, fmaxf(fmaxf(v[i * 4], v[i * 4 + 1]), fmaxf(v[i * 4 + 2], v[i * 4 + 3])));
    }

    __shared__ float red[8];
#pragma unroll
    for (int off = 16; off > 0; off >>= 1)
        mx = fmaxf(mx, __shfl_xor_sync(0xffffffffu, mx, off));
    if ((tid & 31) == 0) red[tid >> 5] = mx;
    __syncthreads();
    if (tid < 32) {
        float m2 = (tid < 8) ? red[tid] : -INFINITY;
#pragma unroll
        for (int off = 4; off > 0; off >>= 1)
            m2 = fmaxf(m2, __shfl_xor_sync(0xffffffffu, m2, off));
        if (tid == 0) red[0] = m2;
    }
    __syncthreads();
    mx = red[0];

    float sum = 0.0f;
#pragma unroll
    for (int i = 0; i < 16; i++) {
        float e = (v[i] != -INFINITY) ? expf(v[i] - mx) : 0.0f;
        v[i] = e;
        sum += e;
    }
#pragma unroll
    for (int off = 16; off > 0; off >>= 1)
        sum += __shfl_xor_sync(0xffffffffu, sum, off);
    __syncthreads();
    if ((tid & 31) == 0) red[tid >> 5] = sum;
    __syncthreads();
    if (tid < 32) {
        float s2 = (tid < 8) ? red[tid] : 0.0f;
#pragma unroll
        for (int off = 4; off > 0; off >>= 1)
            s2 += __shfl_xor_sync(0xffffffffu, s2, off);
        if (tid == 0) red[0] = s2;
    }
    __syncthreads();
    const float inv = 1.0f / red[0];

    if (tid == 0) { g_mx[row] = mx; g_inv[row] = inv; }

#pragma unroll
    for (int i = 0; i < 4; i++) {
        const int c = tid + i * 256;
        h2[c * 2]     = __floats2half2_rn(v[i * 4 + 0] * inv, v[i * 4 + 1] * inv);
        h2[c * 2 + 1] = __floats2half2_rn(v[i * 4 + 2] * inv, v[i * 4 + 3] * inv);
    }
}

// ---------------- softmax pass 2: fp32 weights in place (off critical path) ----
__global__ void __launch_bounds__(256) softmax_p2(
    float* __restrict__ attn, const int* __restrict__ mask)
{
    const int row = blockIdx.x;
    const int b = row / Q_;
    const int4* mrow = (const int4*)(mask + (size_t)b * D_);
    float4* s4 = (float4*)(attn + (size_t)row * D_);
    const int tid = threadIdx.x;
    const float mx = g_mx[row];
    const float inv = g_inv[row];

#pragma unroll
    for (int i = 0; i < 4; i++) {
        const int c = tid + i * 256;
        int4 m = mrow[c];
        float4 x = s4[c];
        float4 o;
        o.x = (m.x != 0) ? expf(x.x - mx) * inv : 0.0f;
        o.y = (m.y != 0) ? expf(x.y - mx) * inv : 0.0f;
        o.z = (m.z != 0) ? expf(x.z - mx) * inv : 0.0f;
        o.w = (m.w != 0) ? expf(x.w - mx) * inv : 0.0f;
        s4[c] = o;
    }
}

// ---------------- launch --------------------------------------------------------
extern "C" void kernel_launch(void* const* d_in, const int* in_sizes, int n_in,
                              void* d_out, int out_size)
{
    const float* query = (const float*)d_in[0];   // [B,Q,H]
    const float* doc   = (const float*)d_in[1];   // [B,D,H]
    const int*   mask  = (const int*)d_in[2];     // [B,D]
    const float* W     = (const float*)d_in[3];   // [H,H]
    const float* bias  = (const float*)d_in[4];   // [H]

    float* out = (float*)d_out;
    float* retrieved = out;                               // [B,Q,H]
    float* attn = out + (size_t)B_ * Q_ * H_;             // [B,Q,D]

    __half *p_q16, *p_query16, *p_W16, *p_doc16, *p_attn16;
    cudaGetSymbolAddress((void**)&p_q16, g_q16);
    cudaGetSymbolAddress((void**)&p_query16, g_query16);
    cudaGetSymbolAddress((void**)&p_W16, g_W16);
    cudaGetSymbolAddress((void**)&p_doc16, g_doc16);
    cudaGetSymbolAddress((void**)&p_attn16, g_attn16);

    cudaFuncSetAttribute(wgemm_h<true, true, true>,
                         cudaFuncAttributeMaxDynamicSharedMemorySize, SMEM_BYTES);
    cudaFuncSetAttribute(wgemm_h<true, false, false>,
                         cudaFuncAttributeMaxDynamicSharedMemorySize, SMEM_BYTES);
    cudaFuncSetAttribute(wgemm_s,
                         cudaFuncAttributeMaxDynamicSharedMemorySize, S_SMEM_BYTES);

    cudaStream_t s2;
    cudaStreamCreateWithFlags(&s2, cudaStreamNonBlocking);
    cudaEvent_t eFork, eDoc, eSm, eP2;
    cudaEventCreateWithFlags(&eFork, cudaEventDisableTiming);
    cudaEventCreateWithFlags(&eDoc, cudaEventDisableTiming);
    cudaEventCreateWithFlags(&eSm, cudaEventDisableTiming);
    cudaEventCreateWithFlags(&eP2, cudaEventDisableTiming);

    const float scale = 1.0f / 32.0f;   // 1/sqrt(H)

    // fork: doc -> fp16 on s2, overlapped with query/W prep + GEMM1
    cudaEventRecord(eFork, 0);
    cudaStreamWaitEvent(s2, eFork, 0);
    k_cvt_h<<<((size_t)B_ * D_ * H_) / 4 / 256, 256, 0, s2>>>(doc, p_doc16);
    cudaEventRecord(eDoc, s2);

    k_cvt_h<<<((size_t)B_ * Q_ * H_) / 4 / 256, 256>>>(query, p_query16);
    k_cvt_h<<<((size_t)H_ * H_) / 4 / 256, 256>>>(W, p_W16);
    // 1) q = query @ W + bias; big-tile kernel, B = W16 [k][n] (trans path)
    {
        dim3 g(H_ / TILE, (B_ * Q_) / TILE, 1);
        wgemm_h<true, true, true><<<g, 256, SMEM_BYTES>>>(
            p_query16, p_W16, p_q16, bias, H_, H_, H_, H_, 1.0f, 0, 0, 0);
    }

    cudaStreamWaitEvent(0, eDoc, 0);
    // 2) scores = q @ doc^T * scale -> attn fp32; SMALL-TILE kernel (3 CTA/SM)
    {
        dim3 g(D_ / 64, Q_ / 128, B_);
        wgemm_s<<<g, 256, S_SMEM_BYTES>>>(
            p_q16, p_doc16, attn, H_, H_, H_, D_, scale,
            (size_t)Q_ * H_, (size_t)D_ * H_, (size_t)Q_ * D_);
    }

    softmax_p1<<<B_ * Q_, 256>>>(attn, mask, p_attn16);

    cudaEventRecord(eSm, 0);
    cudaStreamWaitEvent(s2, eSm, 0);
    softmax_p2<<<B_ * Q_, 256, 0, s2>>>(attn, mask);
    cudaEventRecord(eP2, s2);

    // 4) retrieved = attn @ doc; big-tile kernel, B = doc16 [K,N] (trans path)
    {
        dim3 g(H_ / TILE, Q_ / TILE, B_);
        wgemm_h<true, false, false><<<g, 256, SMEM_BYTES>>>(
            p_attn16, p_doc16, retrieved, nullptr, D_, D_, H_, H_, 1.0f,
            (size_t)Q_ * D_, (size_t)D_ * H_, (size_t)Q_ * H_);
    }

    cudaStreamWaitEvent(0, eP2, 0);
}

// round 17
// speedup vs baseline: 1.0807x; 1.0807x over previous
#include <cuda_runtime.h>
#include <cuda_fp16.h>
#include <math.h>
#include <stdint.h>

#define B_  8
#define Q_  512
#define D_  4096
#define H_  1024

#define STAGES  3
#define TILE    128
#define BK      64                         // k halves per stage
#define STRD_H  72                         // K-major smem row stride (halves)
#define STRD_BN 136                        // trans-B smem row stride (halves)
#define A_HALVES (TILE * STRD_H)           // 9216
#define B_REGION 9216                      // >= max(128*72, 64*136=8704)
#define STAGE_HALVES (A_HALVES + B_REGION) // 18432
#define SMEM_BYTES (STAGES * STAGE_HALVES * 2)   // 110592

// ---------------- scratch (static device memory; no allocs allowed) ----------
__device__ __align__(16) __half g_q16[(size_t)B_ * Q_ * H_];     // projected queries
__device__ __align__(16) __half g_query16[(size_t)B_ * Q_ * H_]; // fp16(query)
__device__ __align__(16) __half g_W16[(size_t)H_ * H_];          // fp16(W) [k][n]
__device__ __align__(16) __half g_doc16[(size_t)B_ * D_ * H_];   // fp16(doc) [B,D,H]
__device__ __align__(16) __half g_attn16[(size_t)B_ * Q_ * D_];  // fp16(attn) [B,Q,D]
__device__ float g_mx[B_ * Q_];                                   // softmax row max
__device__ float g_inv[B_ * Q_];                                  // softmax row 1/sum

// ---------------- helpers -----------------------------------------------------
__device__ __forceinline__ void cp_async16(uint32_t dst, const void* src) {
    asm volatile("cp.async.cg.shared.global [%0], [%1], 16;" :: "r"(dst), "l"(src));
}
#define CP_COMMIT() asm volatile("cp.async.commit_group;" ::: "memory")
#define CP_WAIT(n)  asm volatile("cp.async.wait_group %0;" :: "n"(n) : "memory")

__device__ __forceinline__ uint32_t smem_u32(const void* p) {
    uint32_t a;
    asm("{ .reg .u64 t; cvta.to.shared.u64 t, %1; cvt.u32.u64 %0, t; }" : "=r"(a) : "l"(p));
    return a;
}

__device__ __forceinline__ void ldsm_x4(uint32_t* r, uint32_t addr) {
    asm volatile("ldmatrix.sync.aligned.m8n8.x4.shared.b16 {%0,%1,%2,%3}, [%4];"
                 : "=r"(r[0]), "=r"(r[1]), "=r"(r[2]), "=r"(r[3]) : "r"(addr));
}
__device__ __forceinline__ void ldsm_x4_t(uint32_t* r, uint32_t addr) {
    asm volatile("ldmatrix.sync.aligned.m8n8.x4.trans.shared.b16 {%0,%1,%2,%3}, [%4];"
                 : "=r"(r[0]), "=r"(r[1]), "=r"(r[2]), "=r"(r[3]) : "r"(addr));
}

__device__ __forceinline__ void mma_f16(float* c, const uint32_t* a, const uint32_t* b) {
    asm volatile(
        "mma.sync.aligned.m16n8k16.row.col.f32.f16.f16.f32 "
        "{%0,%1,%2,%3}, {%4,%5,%6,%7}, {%8,%9}, {%0,%1,%2,%3};"
        : "+f"(c[0]), "+f"(c[1]), "+f"(c[2]), "+f"(c[3])
        : "r"(a[0]), "r"(a[1]), "r"(a[2]), "r"(a[3]), "r"(b[0]), "r"(b[1]));
}

// ---------------- warp-MMA FP16 GEMM (CTA 128x128, warp 32x64, BK=64) ---------
// C[m][n] = alpha * sum_k A[m][k] * op(B) (+ bias[n])
//   A: [M,K] K-major fp16, pitch lda.
//   B_TRANS=0: B is [N,K] K-major fp16, pitch ldb. (non-trans ldmatrix)
//   B_TRANS=1: B is [K,N] row-major fp16, pitch ldb. (trans ldmatrix)
// grid: (N/128, M/128, batches), 256 threads, 2 CTAs/SM.
template <bool B_TRANS, bool HAS_BIAS, bool OUT_HALF>
__global__ void __launch_bounds__(256, 2) wgemm_h(
    const __half* __restrict__ A, const __half* __restrict__ Bm,
    void* __restrict__ Cv, const float* __restrict__ bias,
    int K, int lda, int ldb, int ldc, float alpha,
    size_t strideA, size_t strideB, size_t strideC)
{
    extern __shared__ __half smh[];
    const uint32_t sbase = smem_u32(smh);

    const int tid  = threadIdx.x;
    const int lane = tid & 31;
    const int wid  = tid >> 5;
    const int gid  = lane >> 2;
    const int tig  = lane & 3;
    const int warp_m = (wid & 3) * 32;
    const int warp_n = (wid >> 2) * 64;

    const size_t batch = blockIdx.z;
    const __half* Ab = A + batch * strideA + (size_t)(blockIdx.y * TILE) * lda;
    const __half* Bb;
    if (B_TRANS)
        Bb = Bm + batch * strideB + blockIdx.x * TILE;
    else
        Bb = Bm + batch * strideB + (size_t)(blockIdx.x * TILE) * ldb;

    const uint32_t offA = ((uint32_t)(warp_m + (lane & 15)) * STRD_H + ((lane >> 4) << 3)) * 2;
    const uint32_t offB = ((uint32_t)(warp_n + ((lane >> 4) << 3) + (lane & 7)) * STRD_H + (lane & 8)) * 2
                          + A_HALVES * 2;
    const uint32_t offBT = ((uint32_t)((lane & 7) + ((lane >> 3) & 1) * 8) * STRD_BN
                            + warp_n + ((lane >> 4) << 3)) * 2
                          + A_HALVES * 2;

    float acc[2][8][4];
#pragma unroll
    for (int mt = 0; mt < 2; mt++)
#pragma unroll
        for (int nt = 0; nt < 8; nt++)
#pragma unroll
            for (int i = 0; i < 4; i++) acc[mt][nt][i] = 0.0f;

    const int NK = K / BK;

    auto load_stage = [&](int kb) {
        const int s = kb % STAGES;
        const uint32_t stA = sbase + s * STAGE_HALVES * 2;
        const uint32_t stB = stA + A_HALVES * 2;
        const __half* gA = Ab + kb * BK;
#pragma unroll
        for (int r = 0; r < 4; r++) {
            const int c = tid + r * 256;
            const int rw = c >> 3, q = (c & 7) * 8;
            cp_async16(stA + (rw * STRD_H + q) * 2, gA + (size_t)rw * lda + q);
        }
        if (B_TRANS) {
            const __half* gB = Bb + (size_t)(kb * BK) * ldb;
#pragma unroll
            for (int r = 0; r < 4; r++) {
                const int c = tid + r * 256;
                const int rw = c >> 4, q = (c & 15) * 8;
                cp_async16(stB + (rw * STRD_BN + q) * 2, gB + (size_t)rw * ldb + q);
            }
        } else {
            const __half* gB = Bb + kb * BK;
#pragma unroll
            for (int r = 0; r < 4; r++) {
                const int c = tid + r * 256;
                const int rw = c >> 3, q = (c & 7) * 8;
                cp_async16(stB + (rw * STRD_H + q) * 2, gB + (size_t)rw * ldb + q);
            }
        }
    };

    auto ldB = [&](uint32_t* dst, uint32_t stOff, int kk, int p) {
        if (B_TRANS)
            ldsm_x4_t(dst, stOff + offBT + (kk * STRD_BN + p * 16) * 2);
        else
            ldsm_x4(dst, stOff + offB + (p * 16 * STRD_H + kk) * 2);
    };

#pragma unroll
    for (int s = 0; s < STAGES - 1; s++) {
        load_stage(s);
        CP_COMMIT();
    }

    for (int kb = 0; kb < NK; kb++) {
        CP_WAIT(STAGES - 2);
        __syncthreads();          // releases stage (kb-1)%3 AND makes stage kb visible

        const int kn = kb + STAGES - 1;
        if (kn < NK) load_stage(kn);
        CP_COMMIT();

        const uint32_t stOff = sbase + (kb % STAGES) * STAGE_HALVES * 2;
#pragma unroll
        for (int kk = 0; kk < BK; kk += 16) {
            uint32_t a[2][4], b[4][4];
            // interleaved: each LDSM is covered by MMAs on already-loaded frags
            ldB(b[0], stOff, kk, 0);
            ldsm_x4(a[0], stOff + offA + (0 * 16 * STRD_H + kk) * 2);
            ldsm_x4(a[1], stOff + offA + (1 * 16 * STRD_H + kk) * 2);
            ldB(b[1], stOff, kk, 1);

            mma_f16(acc[0][0], a[0], &b[0][0]);
            mma_f16(acc[0][1], a[0], &b[0][2]);
            ldB(b[2], stOff, kk, 2);
            mma_f16(acc[1][0], a[1], &b[0][0]);
            mma_f16(acc[1][1], a[1], &b[0][2]);

            mma_f16(acc[0][2], a[0], &b[1][0]);
            mma_f16(acc[0][3], a[0], &b[1][2]);
            ldB(b[3], stOff, kk, 3);
            mma_f16(acc[1][2], a[1], &b[1][0]);
            mma_f16(acc[1][3], a[1], &b[1][2]);

            mma_f16(acc[0][4], a[0], &b[2][0]);
            mma_f16(acc[0][5], a[0], &b[2][2]);
            mma_f16(acc[1][4], a[1], &b[2][0]);
            mma_f16(acc[1][5], a[1], &b[2][2]);

            mma_f16(acc[0][6], a[0], &b[3][0]);
            mma_f16(acc[0][7], a[0], &b[3][2]);
            mma_f16(acc[1][6], a[1], &b[3][0]);
            mma_f16(acc[1][7], a[1], &b[3][2]);
        }
    }

#pragma unroll
    for (int mt = 0; mt < 2; mt++) {
        const int r0 = blockIdx.y * TILE + warp_m + mt * 16 + gid;
#pragma unroll
        for (int nt = 0; nt < 8; nt++) {
            const int col = blockIdx.x * TILE + warp_n + nt * 8 + 2 * tig;
            float bx = 0.f, by = 0.f;
            if (HAS_BIAS) { bx = __ldg(bias + col); by = __ldg(bias + col + 1); }
            float2 v0, v1;
            v0.x = acc[mt][nt][0] * alpha + bx;
            v0.y = acc[mt][nt][1] * alpha + by;
            v1.x = acc[mt][nt][2] * alpha + bx;
            v1.y = acc[mt][nt][3] * alpha + by;
            if (OUT_HALF) {
                __half* Cb = (__half*)Cv + batch * strideC;
                *(__half2*)(Cb + (size_t)r0 * ldc + col) = __floats2half2_rn(v0.x, v0.y);
                *(__half2*)(Cb + (size_t)(r0 + 8) * ldc + col) = __floats2half2_rn(v1.x, v1.y);
            } else {
                float* Cb = (float*)Cv + batch * strideC;
                *(float2*)(Cb + (size_t)r0 * ldc + col) = v0;
                *(float2*)(Cb + (size_t)(r0 + 8) * ldc + col) = v1;
            }
        }
    }
}

// ---------------- prep: flat fp32 -> fp16 --------------------------------------
__global__ void k_cvt_h(const float* __restrict__ src, __half* __restrict__ dst) {
    size_t i = (size_t)blockIdx.x * blockDim.x + threadIdx.x;
    float4 v = ((const float4*)src)[i];
    ((__half2*)dst)[i * 2]     = __floats2half2_rn(v.x, v.y);
    ((__half2*)dst)[i * 2 + 1] = __floats2half2_rn(v.z, v.w);
}

// ---------------- softmax pass 1: stats + fp16 weights (critical path) ---------
__global__ void __launch_bounds__(256) softmax_p1(
    const float* __restrict__ attn, const int* __restrict__ mask,
    __half* __restrict__ attn16)
{
    const int row = blockIdx.x;
    const int b = row / Q_;
    const int4* mrow = (const int4*)(mask + (size_t)b * D_);
    const float4* s4 = (const float4*)(attn + (size_t)row * D_);
    __half2* h2 = (__half2*)(attn16 + (size_t)row * D_);
    const int tid = threadIdx.x;

    float v[16];
    float mx = -INFINITY;
#pragma unroll
    for (int i = 0; i < 4; i++) {
        const int c = tid + i * 256;
        int4 m = mrow[c];
        float4 x = s4[c];
        v[i * 4 + 0] = (m.x != 0) ? x.x : -INFINITY;
        v[i * 4 + 1] = (m.y != 0) ? x.y : -INFINITY;
        v[i * 4 + 2] = (m.z != 0) ? x.z : -INFINITY;
        v[i * 4 + 3] = (m.w != 0) ? x.w : -INFINITY;
        mx = fmaxf(mx, fmaxf(fmaxf(v[i * 4], v[i * 4 + 1]), fmaxf(v[i * 4 + 2], v[i * 4 + 3])));
    }

    __shared__ float red[8];
#pragma unroll
    for (int off = 16; off > 0; off >>= 1)
        mx = fmaxf(mx, __shfl_xor_sync(0xffffffffu, mx, off));
    if ((tid & 31) == 0) red[tid >> 5] = mx;
    __syncthreads();
    if (tid < 32) {
        float m2 = (tid < 8) ? red[tid] : -INFINITY;
#pragma unroll
        for (int off = 4; off > 0; off >>= 1)
            m2 = fmaxf(m2, __shfl_xor_sync(0xffffffffu, m2, off));
        if (tid == 0) red[0] = m2;
    }
    __syncthreads();
    mx = red[0];

    float sum = 0.0f;
#pragma unroll
    for (int i = 0; i < 16; i++) {
        float e = (v[i] != -INFINITY) ? expf(v[i] - mx) : 0.0f;
        v[i] = e;
        sum += e;
    }
#pragma unroll
    for (int off = 16; off > 0; off >>= 1)
        sum += __shfl_xor_sync(0xffffffffu, sum, off);
    __syncthreads();
    if ((tid & 31) == 0) red[tid >> 5] = sum;
    __syncthreads();
    if (tid < 32) {
        float s2 = (tid < 8) ? red[tid] : 0.0f;
#pragma unroll
        for (int off = 4; off > 0; off >>= 1)
            s2 += __shfl_xor_sync(0xffffffffu, s2, off);
        if (tid == 0) red[0] = s2;
    }
    __syncthreads();
    const float inv = 1.0f / red[0];

    if (tid == 0) { g_mx[row] = mx; g_inv[row] = inv; }

#pragma unroll
    for (int i = 0; i < 4; i++) {
        const int c = tid + i * 256;
        h2[c * 2]     = __floats2half2_rn(v[i * 4 + 0] * inv, v[i * 4 + 1] * inv);
        h2[c * 2 + 1] = __floats2half2_rn(v[i * 4 + 2] * inv, v[i * 4 + 3] * inv);
    }
}

// ---------------- softmax pass 2: fp32 weights in place (off critical path) ----
__global__ void __launch_bounds__(256) softmax_p2(
    float* __restrict__ attn, const int* __restrict__ mask)
{
    const int row = blockIdx.x;
    const int b = row / Q_;
    const int4* mrow = (const int4*)(mask + (size_t)b * D_);
    float4* s4 = (float4*)(attn + (size_t)row * D_);
    const int tid = threadIdx.x;
    const float mx = g_mx[row];
    const float inv = g_inv[row];

#pragma unroll
    for (int i = 0; i < 4; i++) {
        const int c = tid + i * 256;
        int4 m = mrow[c];
        float4 x = s4[c];
        float4 o;
        o.x = (m.x != 0) ? expf(x.x - mx) * inv : 0.0f;
        o.y = (m.y != 0) ? expf(x.y - mx) * inv : 0.0f;
        o.z = (m.z != 0) ? expf(x.z - mx) * inv : 0.0f;
        o.w = (m.w != 0) ? expf(x.w - mx) * inv : 0.0f;
        s4[c] = o;
    }
}

// ---------------- launch --------------------------------------------------------
extern "C" void kernel_launch(void* const* d_in, const int* in_sizes, int n_in,
                              void* d_out, int out_size)
{
    const float* query = (const float*)d_in[0];   // [B,Q,H]
    const float* doc   = (const float*)d_in[1];   // [B,D,H]
    const int*   mask  = (const int*)d_in[2];     // [B,D]
    const float* W     = (const float*)d_in[3];   // [H,H]
    const float* bias  = (const float*)d_in[4];   // [H]

    float* out = (float*)d_out;
    float* retrieved = out;                               // [B,Q,H]
    float* attn = out + (size_t)B_ * Q_ * H_;             // [B,Q,D]

    __half *p_q16, *p_query16, *p_W16, *p_doc16, *p_attn16;
    cudaGetSymbolAddress((void**)&p_q16, g_q16);
    cudaGetSymbolAddress((void**)&p_query16, g_query16);
    cudaGetSymbolAddress((void**)&p_W16, g_W16);
    cudaGetSymbolAddress((void**)&p_doc16, g_doc16);
    cudaGetSymbolAddress((void**)&p_attn16, g_attn16);

    cudaFuncSetAttribute(wgemm_h<true, true, true>,
                         cudaFuncAttributeMaxDynamicSharedMemorySize, SMEM_BYTES);
    cudaFuncSetAttribute(wgemm_h<false, false, false>,
                         cudaFuncAttributeMaxDynamicSharedMemorySize, SMEM_BYTES);
    cudaFuncSetAttribute(wgemm_h<true, false, false>,
                         cudaFuncAttributeMaxDynamicSharedMemorySize, SMEM_BYTES);

    cudaStream_t s2;
    cudaStreamCreateWithFlags(&s2, cudaStreamNonBlocking);
    cudaEvent_t eFork, eDoc, eSm, eP2;
    cudaEventCreateWithFlags(&eFork, cudaEventDisableTiming);
    cudaEventCreateWithFlags(&eDoc, cudaEventDisableTiming);
    cudaEventCreateWithFlags(&eSm, cudaEventDisableTiming);
    cudaEventCreateWithFlags(&eP2, cudaEventDisableTiming);

    const float scale = 1.0f / 32.0f;   // 1/sqrt(H)

    // fork: doc -> fp16 on s2, overlapped with query/W prep + GEMM1
    cudaEventRecord(eFork, 0);
    cudaStreamWaitEvent(s2, eFork, 0);
    k_cvt_h<<<((size_t)B_ * D_ * H_) / 4 / 256, 256, 0, s2>>>(doc, p_doc16);
    cudaEventRecord(eDoc, s2);

    k_cvt_h<<<((size_t)B_ * Q_ * H_) / 4 / 256, 256>>>(query, p_query16);
    k_cvt_h<<<((size_t)H_ * H_) / 4 / 256, 256>>>(W, p_W16);
    // 1) q = query @ W + bias; B = W16 [k][n] (trans path)
    {
        dim3 g(H_ / TILE, (B_ * Q_) / TILE, 1);
        wgemm_h<true, true, true><<<g, 256, SMEM_BYTES>>>(
            p_query16, p_W16, p_q16, bias, H_, H_, H_, H_, 1.0f, 0, 0, 0);
    }

    cudaStreamWaitEvent(0, eDoc, 0);
    // 2) scores = q @ doc^T * scale -> attn fp32; B = doc16 [N,K] (non-trans)
    {
        dim3 g(D_ / TILE, Q_ / TILE, B_);
        wgemm_h<false, false, false><<<g, 256, SMEM_BYTES>>>(
            p_q16, p_doc16, attn, nullptr, H_, H_, H_, D_, scale,
            (size_t)Q_ * H_, (size_t)D_ * H_, (size_t)Q_ * D_);
    }

    softmax_p1<<<B_ * Q_, 256>>>(attn, mask, p_attn16);

    cudaEventRecord(eSm, 0);
    cudaStreamWaitEvent(s2, eSm, 0);
    softmax_p2<<<B_ * Q_, 256, 0, s2>>>(attn, mask);
    cudaEventRecord(eP2, s2);

    // 4) retrieved = attn @ doc; B = doc16 [K,N] (trans path), K = D
    {
        dim3 g(H_ / TILE, Q_ / TILE, B_);
        wgemm_h<true, false, false><<<g, 256, SMEM_BYTES>>>(
            p_attn16, p_doc16, retrieved, nullptr, D_, D_, H_, H_, 1.0f,
            (size_t)Q_ * D_, (size_t)D_ * H_, (size_t)Q_ * H_);
    }

    cudaStreamWaitEvent(0, eP2, 0);
}